// round 2
// baseline (speedup 1.0000x reference)
#include <cuda_runtime.h>
#include <cuda_bf16.h>
#include <cstdint>
#include <cstddef>

#define NB    512
#define NKH   128
#define TT    4096
#define NDOF  8
#define NCOLS (TT * NDOF)   // 32768

// Scratch (allocation-free rule: device globals)
__device__ float g_h2[NB * NKH];                    // h2 activations [b][k]
__device__ float g_f[(size_t)NCOLS * NB];           // forcing term, TRANSPOSED: [col][b]

// ---------------- packed f32x2 helpers ----------------
__device__ __forceinline__ unsigned long long ffma2(unsigned long long a,
                                                    unsigned long long b,
                                                    unsigned long long c) {
    unsigned long long d;
    asm("fma.rn.f32x2 %0, %1, %2, %3;" : "=l"(d) : "l"(a), "l"(b), "l"(c));
    return d;
}
__device__ __forceinline__ unsigned long long dup2(float x) {
    unsigned long long d;
    asm("mov.b64 %0, {%1, %1};" : "=l"(d) : "f"(x));
    return d;
}
union U2 { unsigned long long u; float2 f; };
__device__ __forceinline__ unsigned long long pack2(float a, float b) {
    U2 t; t.f = make_float2(a, b); return t.u;
}

// ---------------- K1: tiny MLP -> h2 ----------------
__global__ void mlp_kernel(const int* __restrict__ cls, const float* __restrict__ z,
                           const float* __restrict__ emb,
                           const float* __restrict__ W1, const float* __restrict__ b1,
                           const float* __restrict__ W2, const float* __restrict__ b2) {
    __shared__ float hin[68];
    __shared__ float h1s[64];
    const int b = blockIdx.x, tid = threadIdx.x;
    if (tid < 64) hin[tid] = z[b * 64 + tid];
    if (tid < 4)  hin[64 + tid] = emb[cls[b] * 4 + tid];
    __syncthreads();
    if (tid < 64) {
        float acc = b1[tid];
        #pragma unroll
        for (int i = 0; i < 68; i++) acc = fmaf(hin[i], W1[i * 64 + tid], acc);
        h1s[tid] = fmaxf(acc, 0.f);
    }
    __syncthreads();
    {
        float acc = b2[tid];
        #pragma unroll
        for (int i = 0; i < 64; i++) acc = fmaf(h1s[i], W2[i * 128 + tid], acc);
        g_h2[b * 128 + tid] = fmaxf(acc, 0.f);
    }
}

// ---------------- K2: GEMM (f32x2) + sigmoid + denorm -> g_f[col][b] ----------------
// C[n][m] = sum_k h2[m][k] * W3[k][n]; block tile 128m x 128n, BK=16, thread tile 8m x 8n
__global__ __launch_bounds__(256)
void gemm_kernel(const float* __restrict__ W3, const float* __restrict__ b3,
                 const float* __restrict__ mn, const float* __restrict__ mx) {
    __shared__ float4 As4[16 * 32];   // As[k][m]  (16 x 128 floats)
    __shared__ float4 Bs4[16 * 32];   // Bs[k][n]  (16 x 128 floats)

    const int tid = threadIdx.x;
    const int tx = tid & 15;          // m micro-tile index
    const int ty = tid >> 4;          // n micro-tile index
    const int n0 = blockIdx.x * 128;
    const int m0 = blockIdx.y * 128;
    const int dof = n0 >> 12;         // 4096 t's per dof, tile never straddles

    unsigned long long acc[8][4];     // [m][n-pair], each holds 2 fp32 outputs
    #pragma unroll
    for (int i = 0; i < 8; i++)
        #pragma unroll
        for (int j = 0; j < 4; j++) acc[i][j] = 0ull;

    // staging registers
    float4 ra0, ra1, rb0, rb1;
    const int am  = tid >> 2;         // 0..63
    const int akq = tid & 3;          // float4 within 16-k slice
    const int bk  = tid >> 4;         // 0..15 (k row)
    const int bn  = tid & 15;         // float4 col

    auto loadStage = [&](int ks) {
        ra0 = *(const float4*)&g_h2[(m0 + am) * 128 + ks * 16 + akq * 4];
        ra1 = *(const float4*)&g_h2[(m0 + am + 64) * 128 + ks * 16 + akq * 4];
        const float4* src = (const float4*)(W3 + (size_t)(ks * 16 + bk) * NCOLS + n0);
        rb0 = src[bn];
        rb1 = src[bn + 16];
    };
    auto storeStage = [&]() {
        float* As = (float*)As4;
        float a0[4] = {ra0.x, ra0.y, ra0.z, ra0.w};
        float a1[4] = {ra1.x, ra1.y, ra1.z, ra1.w};
        #pragma unroll
        for (int j = 0; j < 4; j++) {
            As[(akq * 4 + j) * 128 + am]      = a0[j];
            As[(akq * 4 + j) * 128 + am + 64] = a1[j];
        }
        Bs4[bk * 32 + bn]      = rb0;
        Bs4[bk * 32 + bn + 16] = rb1;
    };

    loadStage(0);
    for (int ks = 0; ks < 8; ks++) {
        __syncthreads();
        storeStage();
        __syncthreads();
        if (ks < 7) loadStage(ks + 1);   // overlap gmem with compute
        #pragma unroll
        for (int kk = 0; kk < 16; kk++) {
            float4 A0 = As4[kk * 32 + tx * 2];
            float4 A1 = As4[kk * 32 + tx * 2 + 1];
            float4 B0 = Bs4[kk * 32 + ty * 2];
            float4 B1 = Bs4[kk * 32 + ty * 2 + 1];
            unsigned long long bp[4] = {pack2(B0.x, B0.y), pack2(B0.z, B0.w),
                                        pack2(B1.x, B1.y), pack2(B1.z, B1.w)};
            float av[8] = {A0.x, A0.y, A0.z, A0.w, A1.x, A1.y, A1.z, A1.w};
            #pragma unroll
            for (int i = 0; i < 8; i++) {
                unsigned long long ad = dup2(av[i]);
                #pragma unroll
                for (int j = 0; j < 4; j++) acc[i][j] = ffma2(ad, bp[j], acc[i][j]);
            }
        }
    }

    // epilogue: bias + sigmoid + denorm, write g_f[n][m] (batch-contiguous)
    const float mnv = mn[dof];
    const float scl = mx[dof] - mnv;
    const int nbase = n0 + ty * 8;
    #pragma unroll
    for (int jj = 0; jj < 8; jj++) {
        const int n = nbase + jj;
        const float bb = b3[n];
        float vals[8];
        #pragma unroll
        for (int i = 0; i < 8; i++) {
            U2 t; t.u = acc[i][jj >> 1];
            float s = (jj & 1) ? t.f.y : t.f.x;
            float zz = s + bb;
            float r = 1.f / (1.f + __expf(-zz));
            vals[i] = fmaf(r, scl, mnv);
        }
        float4* dst = (float4*)(g_f + (size_t)n * NB + m0 + tx * 8);
        dst[0] = make_float4(vals[0], vals[1], vals[2], vals[3]);
        dst[1] = make_float4(vals[4], vals[5], vals[6], vals[7]);
    }
}

// ---------------- K3: chunked scan with decay-warmup halo ----------------
// chain = (dof, b); 8 chunks of 512 steps, 256-step warmup (lambda_max^256 ~ 6e-11)
__global__ void scan_kernel(const float* __restrict__ x0, const float* __restrict__ goal,
                            float* __restrict__ out) {
    const int g = blockIdx.x * blockDim.x + threadIdx.x;   // 32768 threads
    const int b = g & 511;            // warp lanes = consecutive b -> coalesced f loads
    const int r = g >> 9;
    const int dof = r & 7;
    const int chunk = r >> 3;         // 0..7
    const int t0 = chunk * 512;
    const float gl = goal[dof];

    float x, dx;
    int t;
    if (chunk == 0) { x = x0[dof]; dx = 0.f; t = 0; }
    else            { x = gl;      dx = 0.f; t = t0 - 256; }

    const float* fc = g_f + (size_t)(dof * TT) * NB + b;

    // warmup (no writes)
    #pragma unroll 4
    for (; t < t0; t++) {
        float f = fc[(size_t)t * NB];
        float e = gl - x;
        float u = fmaf(6.25f, e, -dx);
        float dd = fmaf(25.f, u, f);
        dx = fmaf(dd, 0.01f, dx);
        x  = fmaf(dx, 0.01f, x);
    }

    float* op = out + (size_t)b * NCOLS + dof * TT + t0;
    for (int tb = 0; tb < 512; tb += 32) {
        float ov[32];
        #pragma unroll
        for (int s = 0; s < 32; s++) {
            float f = fc[(size_t)(t0 + tb + s) * NB];
            float e = gl - x;
            float u = fmaf(6.25f, e, -dx);
            float dd = fmaf(25.f, u, f);
            dx = fmaf(dd, 0.01f, dx);
            x  = fmaf(dx, 0.01f, x);
            ov[s] = x;
        }
        float4* o4 = (float4*)(op + tb);
        #pragma unroll
        for (int q = 0; q < 8; q++)
            o4[q] = make_float4(ov[4 * q], ov[4 * q + 1], ov[4 * q + 2], ov[4 * q + 3]);
    }
}

// ---------------- launch ----------------
extern "C" void kernel_launch(void* const* d_in, const int* in_sizes, int n_in,
                              void* d_out, int out_size) {
    const int*   cls  = (const int*)d_in[0];
    const float* x0   = (const float*)d_in[1];
    const float* goal = (const float*)d_in[2];
    const float* z    = (const float*)d_in[3];
    const float* emb  = (const float*)d_in[4];
    const float* W1   = (const float*)d_in[5];
    const float* b1   = (const float*)d_in[6];
    const float* W2   = (const float*)d_in[7];
    const float* b2   = (const float*)d_in[8];
    const float* W3   = (const float*)d_in[9];
    const float* b3   = (const float*)d_in[10];
    const float* mn   = (const float*)d_in[11];
    const float* mx   = (const float*)d_in[12];
    float* out = (float*)d_out;

    mlp_kernel<<<NB, 128>>>(cls, z, emb, W1, b1, W2, b2);
    gemm_kernel<<<dim3(NCOLS / 128, NB / 128), 256>>>(W3, b3, mn, mx);
    scan_kernel<<<128, 256>>>(x0, goal, out);
}

// round 6
// speedup vs baseline: 1.5965x; 1.5965x over previous
#include <cuda_runtime.h>
#include <cuda_bf16.h>
#include <cstdint>
#include <cstddef>

#define NB    512
#define NKH   128
#define TT    4096
#define NDOF  8
#define NCOLS (TT * NDOF)   // 32768

// ---------------- device-global scratch (allocation-free rule) ----------------
__device__ __nv_bfloat16 g_h2b[NB * NKH];                 // h2 activations bf16 [m][k]
__device__ __nv_bfloat16 g_w3t[(size_t)NCOLS * NKH];      // W3^T bf16 [n][k] (K-major rows)
__device__ float g_f[(size_t)NCOLS * NB];                 // forcing term [col][b]

// ---------------- helpers ----------------
__device__ __forceinline__ uint32_t smem_u32(const void* p) {
    uint32_t a;
    asm("{ .reg .u64 t; cvta.to.shared.u64 t, %1; cvt.u32.u64 %0, t; }" : "=r"(a) : "l"(p));
    return a;
}
__device__ __forceinline__ void cp_async16(uint32_t dst, const void* src) {
    asm volatile("cp.async.cg.shared.global [%0], [%1], 16;" :: "r"(dst), "l"(src) : "memory");
}
__device__ __forceinline__ void cp_commit()  { asm volatile("cp.async.commit_group;" ::: "memory"); }
__device__ __forceinline__ void cp_wait_all(){ asm volatile("cp.async.wait_group 0;" ::: "memory"); }
__device__ __forceinline__ float tanh_approx(float x) {
    float r; asm("tanh.approx.f32 %0, %1;" : "=f"(r) : "f"(x)); return r;
}
__device__ __forceinline__ void ldsm_x4(uint32_t& r0, uint32_t& r1, uint32_t& r2, uint32_t& r3,
                                        uint32_t addr) {
    asm volatile("ldmatrix.sync.aligned.m8n8.x4.shared.b16 {%0,%1,%2,%3}, [%4];"
                 : "=r"(r0), "=r"(r1), "=r"(r2), "=r"(r3) : "r"(addr));
}
__device__ __forceinline__ void mma_bf16(float& c0, float& c1, float& c2, float& c3,
                                         uint32_t a0, uint32_t a1, uint32_t a2, uint32_t a3,
                                         uint32_t b0, uint32_t b1) {
    asm volatile(
        "mma.sync.aligned.m16n8k16.row.col.f32.bf16.bf16.f32 "
        "{%0,%1,%2,%3}, {%4,%5,%6,%7}, {%8,%9}, {%0,%1,%2,%3};"
        : "+f"(c0), "+f"(c1), "+f"(c2), "+f"(c3)
        : "r"(a0), "r"(a1), "r"(a2), "r"(a3), "r"(b0), "r"(b1));
}

// ---------------- K1: tiny MLP -> g_h2b (bf16) ----------------
__global__ __launch_bounds__(128) void mlp_kernel(
        const int* __restrict__ cls, const float* __restrict__ z,
        const float* __restrict__ emb,
        const float* __restrict__ W1, const float* __restrict__ b1,
        const float* __restrict__ W2, const float* __restrict__ b2) {
    __shared__ float W2s[64 * 128];
    __shared__ float hin[68];
    __shared__ float h1s[64];
    const int tid = threadIdx.x;
    for (int i = tid; i < 64 * 128; i += 128) W2s[i] = W2[i];
    __syncthreads();
    for (int bi = 0; bi < 8; bi++) {
        const int b = blockIdx.x * 8 + bi;
        if (tid < 64) hin[tid] = z[b * 64 + tid];
        if (tid < 4)  hin[64 + tid] = emb[cls[b] * 4 + tid];
        __syncthreads();
        if (tid < 64) {
            float acc = b1[tid];
            #pragma unroll
            for (int i = 0; i < 68; i++) acc = fmaf(hin[i], __ldg(&W1[i * 64 + tid]), acc);
            h1s[tid] = fmaxf(acc, 0.f);
        }
        __syncthreads();
        {
            float acc = b2[tid];
            #pragma unroll
            for (int i = 0; i < 64; i++) acc = fmaf(h1s[i], W2s[i * 128 + tid], acc);
            g_h2b[b * 128 + tid] = __float2bfloat16(fmaxf(acc, 0.f));
        }
        __syncthreads();
    }
}

// ---------------- K2: W3 [128][32768] f32 -> g_w3t [32768][128] bf16 ----------------
__global__ __launch_bounds__(256) void transpose_kernel(const float* __restrict__ W3) {
    __shared__ float tile[32][33];
    const int n0 = blockIdx.x * 32, k0 = blockIdx.y * 32;
    const int tx = threadIdx.x, ty = threadIdx.y;   // (32, 8)
    #pragma unroll
    for (int j = 0; j < 32; j += 8)
        tile[ty + j][tx] = W3[(size_t)(k0 + ty + j) * NCOLS + n0 + tx];
    __syncthreads();
    #pragma unroll
    for (int j = 0; j < 32; j += 8)
        g_w3t[(size_t)(n0 + ty + j) * 128 + k0 + tx] = __float2bfloat16(tile[tx][ty + j]);
}

// ---------------- K3: mma.sync bf16 GEMM + sigmoid + denorm -> g_f ----------------
// Block tile: M=128 (batch) x N=64 (cols), K=128 full. 256 threads = 8 warps (2m x 4n),
// warp tile 64x16. Smem: A 32KB + B 16KB = 48KB static. XOR-swizzled 16B chunks.
__global__ __launch_bounds__(256) void gemm_mma_kernel(
        const float* __restrict__ b3, const float* __restrict__ mn,
        const float* __restrict__ mx) {
    __shared__ __align__(128) char smA[128 * 256];   // A: row m -> 256B (128 bf16)
    __shared__ __align__(128) char smB[64 * 256];    // B: row n -> 256B

    const int tid = threadIdx.x;
    const int wid = tid >> 5, lane = tid & 31;
    const int n0 = blockIdx.x * 64;
    const int m0 = blockIdx.y * 128;
    const int dof = n0 >> 12;

    const uint32_t Abase = smem_u32(smA);
    const uint32_t Bbase = smem_u32(smB);

    // ---- stage A (2048 chunks of 16B) and B (1024 chunks) via cp.async ----
    {
        const char* asrc = (const char*)(g_h2b + (size_t)m0 * 128);
        for (int q = tid; q < 2048; q += 256) {
            const int r = q >> 4, c = q & 15;
            cp_async16(Abase + r * 256 + ((c ^ (r & 7)) << 4), asrc + r * 256 + c * 16);
        }
        const char* bsrc = (const char*)(g_w3t + (size_t)n0 * 128);
        for (int q = tid; q < 1024; q += 256) {
            const int r = q >> 4, c = q & 15;
            cp_async16(Bbase + r * 256 + ((c ^ (r & 7)) << 4), bsrc + r * 256 + c * 16);
        }
        cp_commit();
        cp_wait_all();
        __syncthreads();
    }

    // ---- fragment addressing ----
    const int wm = wid & 1;        // 0..1  (m)
    const int wn = wid >> 1;       // 0..3  (n)
    // A ldmatrix.x4 lane mapping: lanes 0-7 m+0..7 (k-lo), 8-15 m+8..15 (k-lo),
    //                             16-23 m+0..7 (k-hi), 24-31 m+8..15 (k-hi)
    const int a_row_in16 = lane & 15;          // m offset within 16
    const int a_kc       = lane >> 4;          // 0 = k-lo chunk, 1 = k-hi
    // B ldmatrix.x4: lanes 0-7 n+0..7 (k-lo), 8-15 n+0..7 (k-hi),
    //                16-23 n+8..15 (k-lo), 24-31 n+8..15 (k-hi)
    const int b_row = wn * 16 + ((lane >> 4) << 3) + (lane & 7);
    const int b_kc  = (lane >> 3) & 1;

    uint32_t aAddrBase[4]; int aS[4];
    #pragma unroll
    for (int fm = 0; fm < 4; fm++) {
        int m = wm * 64 + fm * 16 + a_row_in16;
        aAddrBase[fm] = Abase + m * 256;
        aS[fm] = m & 7;
    }
    const uint32_t bAddrBase = Bbase + b_row * 256;
    const int bS = b_row & 7;

    float acc[4][2][4];
    #pragma unroll
    for (int i = 0; i < 4; i++)
        #pragma unroll
        for (int j = 0; j < 2; j++)
            #pragma unroll
            for (int q = 0; q < 4; q++) acc[i][j][q] = 0.f;

    // ---- main loop: 8 k-steps of 16 ----
    #pragma unroll
    for (int kk = 0; kk < 8; kk++) {
        uint32_t br[4];
        ldsm_x4(br[0], br[1], br[2], br[3],
                bAddrBase + (((kk * 2 + b_kc) ^ bS) << 4));
        #pragma unroll
        for (int fm = 0; fm < 4; fm++) {
            uint32_t ar[4];
            ldsm_x4(ar[0], ar[1], ar[2], ar[3],
                    aAddrBase[fm] + (((kk * 2 + a_kc) ^ aS[fm]) << 4));
            mma_bf16(acc[fm][0][0], acc[fm][0][1], acc[fm][0][2], acc[fm][0][3],
                     ar[0], ar[1], ar[2], ar[3], br[0], br[1]);
            mma_bf16(acc[fm][1][0], acc[fm][1][1], acc[fm][1][2], acc[fm][1][3],
                     ar[0], ar[1], ar[2], ar[3], br[2], br[3]);
        }
    }

    // ---- epilogue: bias + sigmoid + denorm, write g_f[n][b] ----
    const float mnv = mn[dof];
    const float scl = mx[dof] - mnv;
    const float k0 = 0.5f * scl;
    const float k1 = k0 + mnv;

    const int mrow0 = m0 + wm * 64 + (lane >> 2);
    #pragma unroll
    for (int fn = 0; fn < 2; fn++) {
        const int nb = n0 + wn * 16 + fn * 8 + 2 * (lane & 3);
        const float bb0 = __ldg(&b3[nb]);
        const float bb1 = __ldg(&b3[nb + 1]);
        float* g0 = g_f + (size_t)nb * NB;
        float* g1 = g_f + (size_t)(nb + 1) * NB;
        #pragma unroll
        for (int fm = 0; fm < 4; fm++) {
            const int r0 = mrow0 + fm * 16;
            const int r1 = r0 + 8;
            g0[r0] = fmaf(tanh_approx(0.5f * (acc[fm][fn][0] + bb0)), k0, k1);
            g1[r0] = fmaf(tanh_approx(0.5f * (acc[fm][fn][1] + bb1)), k0, k1);
            g0[r1] = fmaf(tanh_approx(0.5f * (acc[fm][fn][2] + bb0)), k0, k1);
            g1[r1] = fmaf(tanh_approx(0.5f * (acc[fm][fn][3] + bb1)), k0, k1);
        }
    }
}

// ---------------- K4: chunked scan with decay-warmup halo ----------------
__global__ void scan_kernel(const float* __restrict__ x0, const float* __restrict__ goal,
                            float* __restrict__ out) {
    const int g = blockIdx.x * blockDim.x + threadIdx.x;   // 32768 threads
    const int b = g & 511;
    const int r = g >> 9;
    const int dof = r & 7;
    const int chunk = r >> 3;         // 0..7
    const int t0 = chunk * 512;
    const float gl = goal[dof];

    float x, dx;
    int t;
    if (chunk == 0) { x = x0[dof]; dx = 0.f; t = 0; }
    else            { x = gl;      dx = 0.f; t = t0 - 256; }

    const float* fc = g_f + (size_t)(dof * TT) * NB + b;

    #pragma unroll 4
    for (; t < t0; t++) {
        float f = fc[(size_t)t * NB];
        float e = gl - x;
        float u = fmaf(6.25f, e, -dx);
        float dd = fmaf(25.f, u, f);
        dx = fmaf(dd, 0.01f, dx);
        x  = fmaf(dx, 0.01f, x);
    }

    float* op = out + (size_t)b * NCOLS + dof * TT + t0;
    for (int tb = 0; tb < 512; tb += 32) {
        float ov[32];
        #pragma unroll
        for (int s = 0; s < 32; s++) {
            float f = fc[(size_t)(t0 + tb + s) * NB];
            float e = gl - x;
            float u = fmaf(6.25f, e, -dx);
            float dd = fmaf(25.f, u, f);
            dx = fmaf(dd, 0.01f, dx);
            x  = fmaf(dx, 0.01f, x);
            ov[s] = x;
        }
        float4* o4 = (float4*)(op + tb);
        #pragma unroll
        for (int q = 0; q < 8; q++)
            o4[q] = make_float4(ov[4 * q], ov[4 * q + 1], ov[4 * q + 2], ov[4 * q + 3]);
    }
}

// ---------------- launch ----------------
extern "C" void kernel_launch(void* const* d_in, const int* in_sizes, int n_in,
                              void* d_out, int out_size) {
    const int*   cls  = (const int*)d_in[0];
    const float* x0   = (const float*)d_in[1];
    const float* goal = (const float*)d_in[2];
    const float* z    = (const float*)d_in[3];
    const float* emb  = (const float*)d_in[4];
    const float* W1   = (const float*)d_in[5];
    const float* b1   = (const float*)d_in[6];
    const float* W2   = (const float*)d_in[7];
    const float* b2   = (const float*)d_in[8];
    const float* W3   = (const float*)d_in[9];
    const float* b3   = (const float*)d_in[10];
    const float* mn   = (const float*)d_in[11];
    const float* mx   = (const float*)d_in[12];
    float* out = (float*)d_out;

    mlp_kernel<<<64, 128>>>(cls, z, emb, W1, b1, W2, b2);
    transpose_kernel<<<dim3(NCOLS / 32, 4), dim3(32, 8)>>>(W3);
    gemm_mma_kernel<<<dim3(NCOLS / 64, NB / 128), 256>>>(b3, mn, mx);
    scan_kernel<<<128, 256>>>(x0, goal, out);
}

// round 8
// speedup vs baseline: 2.3676x; 1.4830x over previous
#include <cuda_runtime.h>
#include <cuda_bf16.h>
#include <cstdint>
#include <cstddef>

#define NB    512
#define NKH   128
#define TT    4096
#define NDOF  8
#define NCOLS (TT * NDOF)   // 32768

// ---------------- device-global scratch (allocation-free rule) ----------------
__device__ __nv_bfloat16 g_h2b[NB * NKH];                 // h2 activations bf16 [m][k]
__device__ __nv_bfloat16 g_w3t[(size_t)NCOLS * NKH];      // W3^T bf16 [n][k] (K-major rows)
__device__ __nv_bfloat16 g_fb[(size_t)NCOLS * NB];        // forcing term bf16 [col][b]

// ---------------- helpers ----------------
__device__ __forceinline__ uint32_t smem_u32(const void* p) {
    uint32_t a;
    asm("{ .reg .u64 t; cvta.to.shared.u64 t, %1; cvt.u32.u64 %0, t; }" : "=r"(a) : "l"(p));
    return a;
}
__device__ __forceinline__ void cp_async16(uint32_t dst, const void* src) {
    asm volatile("cp.async.cg.shared.global [%0], [%1], 16;" :: "r"(dst), "l"(src) : "memory");
}
__device__ __forceinline__ void cp_commit()  { asm volatile("cp.async.commit_group;" ::: "memory"); }
__device__ __forceinline__ void cp_wait_all(){ asm volatile("cp.async.wait_group 0;" ::: "memory"); }
__device__ __forceinline__ float tanh_approx(float x) {
    float r; asm("tanh.approx.f32 %0, %1;" : "=f"(r) : "f"(x)); return r;
}
__device__ __forceinline__ void ldsm_x4(uint32_t& r0, uint32_t& r1, uint32_t& r2, uint32_t& r3,
                                        uint32_t addr) {
    asm volatile("ldmatrix.sync.aligned.m8n8.x4.shared.b16 {%0,%1,%2,%3}, [%4];"
                 : "=r"(r0), "=r"(r1), "=r"(r2), "=r"(r3) : "r"(addr));
}
__device__ __forceinline__ void mma_bf16(float& c0, float& c1, float& c2, float& c3,
                                         uint32_t a0, uint32_t a1, uint32_t a2, uint32_t a3,
                                         uint32_t b0, uint32_t b1) {
    asm volatile(
        "mma.sync.aligned.m16n8k16.row.col.f32.bf16.bf16.f32 "
        "{%0,%1,%2,%3}, {%4,%5,%6,%7}, {%8,%9}, {%0,%1,%2,%3};"
        : "+f"(c0), "+f"(c1), "+f"(c2), "+f"(c3)
        : "r"(a0), "r"(a1), "r"(a2), "r"(a3), "r"(b0), "r"(b1));
}

// ---------------- K1: tiny MLP -> g_h2b (bf16) ----------------
__global__ __launch_bounds__(128) void mlp_kernel(
        const int* __restrict__ cls, const float* __restrict__ z,
        const float* __restrict__ emb,
        const float* __restrict__ W1, const float* __restrict__ b1,
        const float* __restrict__ W2, const float* __restrict__ b2) {
    __shared__ float W2s[64 * 128];
    __shared__ float hin[68];
    __shared__ float h1s[64];
    const int tid = threadIdx.x;
    for (int i = tid; i < 64 * 128; i += 128) W2s[i] = W2[i];
    __syncthreads();
    for (int bi = 0; bi < 8; bi++) {
        const int b = blockIdx.x * 8 + bi;
        if (tid < 64) hin[tid] = z[b * 64 + tid];
        if (tid < 4)  hin[64 + tid] = emb[cls[b] * 4 + tid];
        __syncthreads();
        if (tid < 64) {
            float acc = b1[tid];
            #pragma unroll
            for (int i = 0; i < 68; i++) acc = fmaf(hin[i], __ldg(&W1[i * 64 + tid]), acc);
            h1s[tid] = fmaxf(acc, 0.f);
        }
        __syncthreads();
        {
            float acc = b2[tid];
            #pragma unroll
            for (int i = 0; i < 64; i++) acc = fmaf(h1s[i], W2s[i * 128 + tid], acc);
            g_h2b[b * 128 + tid] = __float2bfloat16(fmaxf(acc, 0.f));
        }
        __syncthreads();
    }
}

// ---------------- K2: W3 [128][32768] f32 -> g_w3t [32768][128] bf16 ----------------
__global__ __launch_bounds__(256) void transpose_kernel(const float* __restrict__ W3) {
    __shared__ float tile[32][33];
    const int n0 = blockIdx.x * 32, k0 = blockIdx.y * 32;
    const int tx = threadIdx.x, ty = threadIdx.y;   // (32, 8)
    #pragma unroll
    for (int j = 0; j < 32; j += 8)
        tile[ty + j][tx] = W3[(size_t)(k0 + ty + j) * NCOLS + n0 + tx];
    __syncthreads();
    #pragma unroll
    for (int j = 0; j < 32; j += 8)
        g_w3t[(size_t)(n0 + ty + j) * 128 + k0 + tx] = __float2bfloat16(tile[tx][ty + j]);
}

// ---------------- K3: mma.sync bf16 GEMM + sigmoid + denorm -> g_fb ----------------
// Block tile: M=128 (batch) x N=64 (cols), K=128 full. 256 threads = 8 warps (2m x 4n),
// warp tile 64x16. Smem: A 32KB + B 16KB = 48KB static. XOR-swizzled 16B chunks.
__global__ __launch_bounds__(256) void gemm_mma_kernel(
        const float* __restrict__ b3, const float* __restrict__ mn,
        const float* __restrict__ mx) {
    __shared__ __align__(128) char smA[128 * 256];   // A: row m -> 256B (128 bf16)
    __shared__ __align__(128) char smB[64 * 256];    // B: row n -> 256B

    const int tid = threadIdx.x;
    const int wid = tid >> 5, lane = tid & 31;
    const int n0 = blockIdx.x * 64;
    const int m0 = blockIdx.y * 128;
    const int dof = n0 >> 12;

    const uint32_t Abase = smem_u32(smA);
    const uint32_t Bbase = smem_u32(smB);

    // ---- stage A (2048 chunks of 16B) and B (1024 chunks) via cp.async ----
    {
        const char* asrc = (const char*)(g_h2b + (size_t)m0 * 128);
        for (int q = tid; q < 2048; q += 256) {
            const int r = q >> 4, c = q & 15;
            cp_async16(Abase + r * 256 + ((c ^ (r & 7)) << 4), asrc + r * 256 + c * 16);
        }
        const char* bsrc = (const char*)(g_w3t + (size_t)n0 * 128);
        for (int q = tid; q < 1024; q += 256) {
            const int r = q >> 4, c = q & 15;
            cp_async16(Bbase + r * 256 + ((c ^ (r & 7)) << 4), bsrc + r * 256 + c * 16);
        }
        cp_commit();
        cp_wait_all();
        __syncthreads();
    }

    // ---- fragment addressing ----
    const int wm = wid & 1;        // 0..1  (m)
    const int wn = wid >> 1;       // 0..3  (n)
    const int a_row_in16 = lane & 15;
    const int a_kc       = lane >> 4;
    const int b_row = wn * 16 + ((lane >> 4) << 3) + (lane & 7);
    const int b_kc  = (lane >> 3) & 1;

    uint32_t aAddrBase[4]; int aS[4];
    #pragma unroll
    for (int fm = 0; fm < 4; fm++) {
        int m = wm * 64 + fm * 16 + a_row_in16;
        aAddrBase[fm] = Abase + m * 256;
        aS[fm] = m & 7;
    }
    const uint32_t bAddrBase = Bbase + b_row * 256;
    const int bS = b_row & 7;

    float acc[4][2][4];
    #pragma unroll
    for (int i = 0; i < 4; i++)
        #pragma unroll
        for (int j = 0; j < 2; j++)
            #pragma unroll
            for (int q = 0; q < 4; q++) acc[i][j][q] = 0.f;

    // ---- main loop: 8 k-steps of 16 ----
    #pragma unroll
    for (int kk = 0; kk < 8; kk++) {
        uint32_t br[4];
        ldsm_x4(br[0], br[1], br[2], br[3],
                bAddrBase + (((kk * 2 + b_kc) ^ bS) << 4));
        #pragma unroll
        for (int fm = 0; fm < 4; fm++) {
            uint32_t ar[4];
            ldsm_x4(ar[0], ar[1], ar[2], ar[3],
                    aAddrBase[fm] + (((kk * 2 + a_kc) ^ aS[fm]) << 4));
            mma_bf16(acc[fm][0][0], acc[fm][0][1], acc[fm][0][2], acc[fm][0][3],
                     ar[0], ar[1], ar[2], ar[3], br[0], br[1]);
            mma_bf16(acc[fm][1][0], acc[fm][1][1], acc[fm][1][2], acc[fm][1][3],
                     ar[0], ar[1], ar[2], ar[3], br[2], br[3]);
        }
    }

    // ---- epilogue: bias + sigmoid + denorm, write g_fb[n][b] (bf16) ----
    const float mnv = mn[dof];
    const float scl = mx[dof] - mnv;
    const float k0 = 0.5f * scl;
    const float k1 = k0 + mnv;

    const int mrow0 = m0 + wm * 64 + (lane >> 2);
    #pragma unroll
    for (int fn = 0; fn < 2; fn++) {
        const int nb = n0 + wn * 16 + fn * 8 + 2 * (lane & 3);
        const float bb0 = __ldg(&b3[nb]);
        const float bb1 = __ldg(&b3[nb + 1]);
        __nv_bfloat16* g0 = g_fb + (size_t)nb * NB;
        __nv_bfloat16* g1 = g_fb + (size_t)(nb + 1) * NB;
        #pragma unroll
        for (int fm = 0; fm < 4; fm++) {
            const int r0 = mrow0 + fm * 16;
            const int r1 = r0 + 8;
            g0[r0] = __float2bfloat16(fmaf(tanh_approx(0.5f * (acc[fm][fn][0] + bb0)), k0, k1));
            g1[r0] = __float2bfloat16(fmaf(tanh_approx(0.5f * (acc[fm][fn][1] + bb1)), k0, k1));
            g0[r1] = __float2bfloat16(fmaf(tanh_approx(0.5f * (acc[fm][fn][2] + bb0)), k0, k1));
            g1[r1] = __float2bfloat16(fmaf(tanh_approx(0.5f * (acc[fm][fn][3] + bb1)), k0, k1));
        }
    }
}

// ---------------- K4: chunked scan, steady-state init + 128-step warmup ----------------
// chain = (dof, b, chunk); 16 chunks of 256 steps. Init at local equilibrium
// x = goal + f/156.25 (dx=0); residual decays by 0.912^128 ~ 7.5e-6.
__global__ __launch_bounds__(256) void scan_kernel(
        const float* __restrict__ x0, const float* __restrict__ goal,
        float* __restrict__ out) {
    const int g = blockIdx.x * blockDim.x + threadIdx.x;   // 65536 threads
    const int b = g & 511;            // warp lanes = consecutive b -> coalesced f loads
    const int r = g >> 9;
    const int dof = r & 7;
    const int chunk = r >> 3;         // 0..15
    const int t0 = chunk * 256;
    const float gl = goal[dof];

    const __nv_bfloat16* fc = g_fb + (size_t)(dof * TT) * NB + b;

    float x, dx;
    int t;
    if (chunk == 0) {
        x = x0[dof]; dx = 0.f; t = 0;
    } else {
        t = t0 - 128;
        float f0 = __bfloat162float(fc[(size_t)t * NB]);
        x = fmaf(f0, 1.f / 156.25f, gl);   // steady state for constant f
        dx = 0.f;
    }

    // warmup (no writes)
    #pragma unroll 4
    for (; t < t0; t++) {
        float f = __bfloat162float(fc[(size_t)t * NB]);
        float e = gl - x;
        float u = fmaf(6.25f, e, -dx);
        float dd = fmaf(25.f, u, f);
        dx = fmaf(dd, 0.01f, dx);
        x  = fmaf(dx, 0.01f, x);
    }

    float* op = out + (size_t)b * NCOLS + dof * TT + t0;
    for (int tb = 0; tb < 256; tb += 32) {
        float ov[32];
        #pragma unroll
        for (int s = 0; s < 32; s++) {
            float f = __bfloat162float(fc[(size_t)(t0 + tb + s) * NB]);
            float e = gl - x;
            float u = fmaf(6.25f, e, -dx);
            float dd = fmaf(25.f, u, f);
            dx = fmaf(dd, 0.01f, dx);
            x  = fmaf(dx, 0.01f, x);
            ov[s] = x;
        }
        float4* o4 = (float4*)(op + tb);
        #pragma unroll
        for (int q = 0; q < 8; q++)
            o4[q] = make_float4(ov[4 * q], ov[4 * q + 1], ov[4 * q + 2], ov[4 * q + 3]);
    }
}

// ---------------- launch ----------------
extern "C" void kernel_launch(void* const* d_in, const int* in_sizes, int n_in,
                              void* d_out, int out_size) {
    const int*   cls  = (const int*)d_in[0];
    const float* x0   = (const float*)d_in[1];
    const float* goal = (const float*)d_in[2];
    const float* z    = (const float*)d_in[3];
    const float* emb  = (const float*)d_in[4];
    const float* W1   = (const float*)d_in[5];
    const float* b1   = (const float*)d_in[6];
    const float* W2   = (const float*)d_in[7];
    const float* b2   = (const float*)d_in[8];
    const float* W3   = (const float*)d_in[9];
    const float* b3   = (const float*)d_in[10];
    const float* mn   = (const float*)d_in[11];
    const float* mx   = (const float*)d_in[12];
    float* out = (float*)d_out;

    mlp_kernel<<<64, 128>>>(cls, z, emb, W1, b1, W2, b2);
    transpose_kernel<<<dim3(NCOLS / 32, 4), dim3(32, 8)>>>(W3);
    gemm_mma_kernel<<<dim3(NCOLS / 64, NB / 128), 256>>>(b3, mn, mx);
    scan_kernel<<<256, 256>>>(x0, goal, out);
}

// round 9
// speedup vs baseline: 2.4381x; 1.0298x over previous
#include <cuda_runtime.h>
#include <cuda_bf16.h>
#include <cstdint>
#include <cstddef>

#define NB    512
#define NKH   128
#define TT    4096
#define NDOF  8
#define NCOLS (TT * NDOF)   // 32768

// ---------------- device-global scratch (allocation-free rule) ----------------
__device__ __nv_bfloat16 g_h2b[NB * NKH];                 // h2 activations bf16 [m][k]
__device__ __nv_bfloat16 g_w3t[(size_t)NCOLS * NKH];      // W3^T bf16 [n][k] (K-major rows)
__device__ __nv_bfloat16 g_fb[(size_t)NCOLS * NB];        // forcing term bf16 [col][b]

// ---------------- helpers ----------------
__device__ __forceinline__ uint32_t smem_u32(const void* p) {
    uint32_t a;
    asm("{ .reg .u64 t; cvta.to.shared.u64 t, %1; cvt.u32.u64 %0, t; }" : "=r"(a) : "l"(p));
    return a;
}
__device__ __forceinline__ void cp_async16(uint32_t dst, const void* src) {
    asm volatile("cp.async.cg.shared.global [%0], [%1], 16;" :: "r"(dst), "l"(src) : "memory");
}
__device__ __forceinline__ void cp_commit()  { asm volatile("cp.async.commit_group;" ::: "memory"); }
__device__ __forceinline__ void cp_wait_all(){ asm volatile("cp.async.wait_group 0;" ::: "memory"); }
__device__ __forceinline__ float tanh_approx(float x) {
    float r; asm("tanh.approx.f32 %0, %1;" : "=f"(r) : "f"(x)); return r;
}
__device__ __forceinline__ void ldsm_x4(uint32_t& r0, uint32_t& r1, uint32_t& r2, uint32_t& r3,
                                        uint32_t addr) {
    asm volatile("ldmatrix.sync.aligned.m8n8.x4.shared.b16 {%0,%1,%2,%3}, [%4];"
                 : "=r"(r0), "=r"(r1), "=r"(r2), "=r"(r3) : "r"(addr));
}
__device__ __forceinline__ void mma_bf16(float& c0, float& c1, float& c2, float& c3,
                                         uint32_t a0, uint32_t a1, uint32_t a2, uint32_t a3,
                                         uint32_t b0, uint32_t b1) {
    asm volatile(
        "mma.sync.aligned.m16n8k16.row.col.f32.bf16.bf16.f32 "
        "{%0,%1,%2,%3}, {%4,%5,%6,%7}, {%8,%9}, {%0,%1,%2,%3};"
        : "+f"(c0), "+f"(c1), "+f"(c2), "+f"(c3)
        : "r"(a0), "r"(a1), "r"(a2), "r"(a3), "r"(b0), "r"(b1));
}

// ---------------- K1: tiny MLP -> g_h2b (bf16) ----------------
__global__ __launch_bounds__(128) void mlp_kernel(
        const int* __restrict__ cls, const float* __restrict__ z,
        const float* __restrict__ emb,
        const float* __restrict__ W1, const float* __restrict__ b1,
        const float* __restrict__ W2, const float* __restrict__ b2) {
    __shared__ float W2s[64 * 128];
    __shared__ float hin[68];
    __shared__ float h1s[64];
    const int tid = threadIdx.x;
    for (int i = tid; i < 64 * 128; i += 128) W2s[i] = W2[i];
    __syncthreads();
    for (int bi = 0; bi < 8; bi++) {
        const int b = blockIdx.x * 8 + bi;
        if (tid < 64) hin[tid] = z[b * 64 + tid];
        if (tid < 4)  hin[64 + tid] = emb[cls[b] * 4 + tid];
        __syncthreads();
        if (tid < 64) {
            float acc = b1[tid];
            #pragma unroll
            for (int i = 0; i < 68; i++) acc = fmaf(hin[i], __ldg(&W1[i * 64 + tid]), acc);
            h1s[tid] = fmaxf(acc, 0.f);
        }
        __syncthreads();
        {
            float acc = b2[tid];
            #pragma unroll
            for (int i = 0; i < 64; i++) acc = fmaf(h1s[i], W2s[i * 128 + tid], acc);
            g_h2b[b * 128 + tid] = __float2bfloat16(fmaxf(acc, 0.f));
        }
        __syncthreads();
    }
}

// ---------------- K2: W3 [128][32768] f32 -> g_w3t [32768][128] bf16 ----------------
__global__ __launch_bounds__(256) void transpose_kernel(const float* __restrict__ W3) {
    __shared__ float tile[32][33];
    const int n0 = blockIdx.x * 32, k0 = blockIdx.y * 32;
    const int tx = threadIdx.x, ty = threadIdx.y;   // (32, 8)
    #pragma unroll
    for (int j = 0; j < 32; j += 8)
        tile[ty + j][tx] = W3[(size_t)(k0 + ty + j) * NCOLS + n0 + tx];
    __syncthreads();
    #pragma unroll
    for (int j = 0; j < 32; j += 8)
        g_w3t[(size_t)(n0 + ty + j) * 128 + k0 + tx] = __float2bfloat16(tile[tx][ty + j]);
}

// ---------------- K3: mma.sync bf16 GEMM + sigmoid + denorm -> g_fb ----------------
// Block tile: M=128 (batch) x N=64 (cols), K=128 full. 256 threads = 8 warps (2m x 4n),
// warp tile 64x16. Smem: A 32KB + B 16KB = 48KB static. XOR-swizzled 16B chunks.
__global__ __launch_bounds__(256) void gemm_mma_kernel(
        const float* __restrict__ b3, const float* __restrict__ mn,
        const float* __restrict__ mx) {
    __shared__ __align__(128) char smA[128 * 256];   // A: row m -> 256B (128 bf16)
    __shared__ __align__(128) char smB[64 * 256];    // B: row n -> 256B

    const int tid = threadIdx.x;
    const int wid = tid >> 5, lane = tid & 31;
    const int n0 = blockIdx.x * 64;
    const int m0 = blockIdx.y * 128;
    const int dof = n0 >> 12;

    const uint32_t Abase = smem_u32(smA);
    const uint32_t Bbase = smem_u32(smB);

    // ---- stage A (2048 chunks of 16B) and B (1024 chunks) via cp.async ----
    {
        const char* asrc = (const char*)(g_h2b + (size_t)m0 * 128);
        for (int q = tid; q < 2048; q += 256) {
            const int r = q >> 4, c = q & 15;
            cp_async16(Abase + r * 256 + ((c ^ (r & 7)) << 4), asrc + r * 256 + c * 16);
        }
        const char* bsrc = (const char*)(g_w3t + (size_t)n0 * 128);
        for (int q = tid; q < 1024; q += 256) {
            const int r = q >> 4, c = q & 15;
            cp_async16(Bbase + r * 256 + ((c ^ (r & 7)) << 4), bsrc + r * 256 + c * 16);
        }
        cp_commit();
        cp_wait_all();
        __syncthreads();
    }

    // ---- fragment addressing ----
    const int wm = wid & 1;        // 0..1  (m)
    const int wn = wid >> 1;       // 0..3  (n)
    const int a_row_in16 = lane & 15;
    const int a_kc       = lane >> 4;
    const int b_row = wn * 16 + ((lane >> 4) << 3) + (lane & 7);
    const int b_kc  = (lane >> 3) & 1;

    uint32_t aAddrBase[4]; int aS[4];
    #pragma unroll
    for (int fm = 0; fm < 4; fm++) {
        int m = wm * 64 + fm * 16 + a_row_in16;
        aAddrBase[fm] = Abase + m * 256;
        aS[fm] = m & 7;
    }
    const uint32_t bAddrBase = Bbase + b_row * 256;
    const int bS = b_row & 7;

    float acc[4][2][4];
    #pragma unroll
    for (int i = 0; i < 4; i++)
        #pragma unroll
        for (int j = 0; j < 2; j++)
            #pragma unroll
            for (int q = 0; q < 4; q++) acc[i][j][q] = 0.f;

    // ---- main loop: 8 k-steps of 16 ----
    #pragma unroll
    for (int kk = 0; kk < 8; kk++) {
        uint32_t br[4];
        ldsm_x4(br[0], br[1], br[2], br[3],
                bAddrBase + (((kk * 2 + b_kc) ^ bS) << 4));
        #pragma unroll
        for (int fm = 0; fm < 4; fm++) {
            uint32_t ar[4];
            ldsm_x4(ar[0], ar[1], ar[2], ar[3],
                    aAddrBase[fm] + (((kk * 2 + a_kc) ^ aS[fm]) << 4));
            mma_bf16(acc[fm][0][0], acc[fm][0][1], acc[fm][0][2], acc[fm][0][3],
                     ar[0], ar[1], ar[2], ar[3], br[0], br[1]);
            mma_bf16(acc[fm][1][0], acc[fm][1][1], acc[fm][1][2], acc[fm][1][3],
                     ar[0], ar[1], ar[2], ar[3], br[2], br[3]);
        }
    }

    // ---- epilogue: bias + sigmoid + denorm, write g_fb[n][b] (bf16) ----
    const float mnv = mn[dof];
    const float scl = mx[dof] - mnv;
    const float k0 = 0.5f * scl;
    const float k1 = k0 + mnv;

    const int mrow0 = m0 + wm * 64 + (lane >> 2);
    #pragma unroll
    for (int fn = 0; fn < 2; fn++) {
        const int nb = n0 + wn * 16 + fn * 8 + 2 * (lane & 3);
        const float bb0 = __ldg(&b3[nb]);
        const float bb1 = __ldg(&b3[nb + 1]);
        __nv_bfloat16* g0 = g_fb + (size_t)nb * NB;
        __nv_bfloat16* g1 = g_fb + (size_t)(nb + 1) * NB;
        #pragma unroll
        for (int fm = 0; fm < 4; fm++) {
            const int r0 = mrow0 + fm * 16;
            const int r1 = r0 + 8;
            g0[r0] = __float2bfloat16(fmaf(tanh_approx(0.5f * (acc[fm][fn][0] + bb0)), k0, k1));
            g1[r0] = __float2bfloat16(fmaf(tanh_approx(0.5f * (acc[fm][fn][1] + bb1)), k0, k1));
            g0[r1] = __float2bfloat16(fmaf(tanh_approx(0.5f * (acc[fm][fn][2] + bb0)), k0, k1));
            g1[r1] = __float2bfloat16(fmaf(tanh_approx(0.5f * (acc[fm][fn][3] + bb1)), k0, k1));
        }
    }
}

// ---------------- K4: chunked scan, short-chain affine form ----------------
// Composed one-step update (algebraically == reference step):
//   dx' = 0.75*dx + (-1.5625*x + c1),  c1 = 1.5625*g + 0.01*f
//   x'  = 0.0075*dx + (0.984375*x + c2), c2 = 0.015625*g + 0.0001*f
// Critical path: 2 chained FMAs (8 cyc) vs 5 (20 cyc) for the naive form.
// 32 chunks of 128 steps; 96-step warmup from steady-state init
// (lambda_max^96 ~ 1.3e-4 -> residual ~4e-5 abs).
__global__ __launch_bounds__(256) void scan_kernel(
        const float* __restrict__ x0, const float* __restrict__ goal,
        float* __restrict__ out) {
    const int g = blockIdx.x * blockDim.x + threadIdx.x;   // 131072 threads
    const int b = g & 511;            // warp lanes = consecutive b -> coalesced f loads
    const int r = g >> 9;
    const int dof = r & 7;
    const int chunk = r >> 3;         // 0..31
    const int t0 = chunk * 128;
    const float gl = goal[dof];
    const float c1g = 1.5625f * gl;
    const float c2g = 0.015625f * gl;

    const __nv_bfloat16* fc = g_fb + (size_t)(dof * TT) * NB + b;

    float x, dx;
    int t;
    if (chunk == 0) {
        x = x0[dof]; dx = 0.f; t = 0;
    } else {
        t = t0 - 96;
        float f0 = __bfloat162float(fc[(size_t)t * NB]);
        x = fmaf(f0, 1.f / 156.25f, gl);   // steady state for constant f
        dx = 0.f;
    }

    // warmup (no writes)
    #pragma unroll 8
    for (; t < t0; t++) {
        float f = __bfloat162float(fc[(size_t)t * NB]);
        float cf1 = fmaf(0.01f, f, c1g);
        float cf2 = fmaf(0.0001f, f, c2g);
        float nx = fmaf(0.0075f, dx, fmaf(0.984375f, x, cf2));
        dx = fmaf(0.75f, dx, fmaf(-1.5625f, x, cf1));
        x = nx;
    }

    float* op = out + (size_t)b * NCOLS + dof * TT + t0;
    for (int tb = 0; tb < 128; tb += 16) {
        float ov[16];
        #pragma unroll
        for (int s = 0; s < 16; s++) {
            float f = __bfloat162float(fc[(size_t)(t0 + tb + s) * NB]);
            float cf1 = fmaf(0.01f, f, c1g);
            float cf2 = fmaf(0.0001f, f, c2g);
            float nx = fmaf(0.0075f, dx, fmaf(0.984375f, x, cf2));
            dx = fmaf(0.75f, dx, fmaf(-1.5625f, x, cf1));
            x = nx;
            ov[s] = x;
        }
        float4* o4 = (float4*)(op + tb);
        #pragma unroll
        for (int q = 0; q < 4; q++)
            o4[q] = make_float4(ov[4 * q], ov[4 * q + 1], ov[4 * q + 2], ov[4 * q + 3]);
    }
}

// ---------------- launch ----------------
extern "C" void kernel_launch(void* const* d_in, const int* in_sizes, int n_in,
                              void* d_out, int out_size) {
    const int*   cls  = (const int*)d_in[0];
    const float* x0   = (const float*)d_in[1];
    const float* goal = (const float*)d_in[2];
    const float* z    = (const float*)d_in[3];
    const float* emb  = (const float*)d_in[4];
    const float* W1   = (const float*)d_in[5];
    const float* b1   = (const float*)d_in[6];
    const float* W2   = (const float*)d_in[7];
    const float* b2   = (const float*)d_in[8];
    const float* W3   = (const float*)d_in[9];
    const float* b3   = (const float*)d_in[10];
    const float* mn   = (const float*)d_in[11];
    const float* mx   = (const float*)d_in[12];
    float* out = (float*)d_out;

    mlp_kernel<<<64, 128>>>(cls, z, emb, W1, b1, W2, b2);
    transpose_kernel<<<dim3(NCOLS / 32, 4), dim3(32, 8)>>>(W3);
    gemm_mma_kernel<<<dim3(NCOLS / 64, NB / 128), 256>>>(b3, mn, mx);
    scan_kernel<<<512, 256>>>(x0, goal, out);
}